// round 5
// baseline (speedup 1.0000x reference)
#include <cuda_runtime.h>
#include <cuda_bf16.h>
#include <math.h>

#define N_NODES 50000
#define N_EDGES 800000
#define D 128
#define C 32
#define G 64
#define EPS 1e-5f
#define NUM_LAYERS 3

// ---------------- scratch (device globals; no allocation allowed) ----------
__device__ float    g_bufA[N_NODES * D];
__device__ float    g_bufB[N_NODES * D];
__device__ float    g_pooled[G * D];
__device__ unsigned g_Wcat[NUM_LAYERS * 2 * D * D];   // tf32 [l][256][128]
__device__ int      g_deg[N_NODES];
__device__ int      g_rowptr[N_NODES + 1];
__device__ int      g_cursor[N_NODES];
__device__ int      g_col[N_EDGES];
__device__ int      g_goff[G + 1];

__device__ __forceinline__ unsigned f2tf(float f) {
    unsigned u;
    asm("cvt.rna.tf32.f32 %0, %1;" : "=r"(u) : "f"(f));
    return u;
}

__device__ __forceinline__ void mma_tf32(float* d, const unsigned* a, const unsigned* b) {
    asm volatile(
        "mma.sync.aligned.m16n8k8.row.col.f32.tf32.tf32.f32 "
        "{%0,%1,%2,%3}, {%4,%5,%6,%7}, {%8,%9}, {%0,%1,%2,%3};"
        : "+f"(d[0]), "+f"(d[1]), "+f"(d[2]), "+f"(d[3])
        : "r"(a[0]), "r"(a[1]), "r"(a[2]), "r"(a[3]), "r"(b[0]), "r"(b[1]));
}

// ---------------- CSR build ------------------------------------------------
__global__ void k_count_deg(const int* __restrict__ ei) {
    int e = blockIdx.x * blockDim.x + threadIdx.x;
    if (e < N_EDGES) atomicAdd(&g_deg[ei[N_EDGES + e]], 1);
}

__global__ void k_scan() {
    __shared__ int s[1024];
    const int t = threadIdx.x;
    const int ITEMS = (N_NODES + 1023) / 1024;  // 49
    int base = t * ITEMS;
    int loc = 0;
    for (int i = 0; i < ITEMS; i++) {
        int idx = base + i;
        if (idx < N_NODES) loc += g_deg[idx];
    }
    s[t] = loc;
    __syncthreads();
    for (int off = 1; off < 1024; off <<= 1) {
        int v = 0;
        if (t >= off) v = s[t - off];
        __syncthreads();
        s[t] += v;
        __syncthreads();
    }
    int run = (t == 0) ? 0 : s[t - 1];
    for (int i = 0; i < ITEMS; i++) {
        int idx = base + i;
        if (idx < N_NODES) {
            g_rowptr[idx] = run;
            g_cursor[idx] = run;
            run += g_deg[idx];
        }
    }
    if (t == 1023) g_rowptr[N_NODES] = s[1023];
}

__global__ void k_fill_csr(const int* __restrict__ ei) {
    int e = blockIdx.x * blockDim.x + threadIdx.x;
    if (e < N_EDGES) {
        int dst = ei[N_EDGES + e];
        int pos = atomicAdd(&g_cursor[dst], 1);
        g_col[pos] = ei[e];
    }
}

__global__ void k_goff(const int* __restrict__ batch) {
    int n = blockIdx.x * blockDim.x + threadIdx.x;
    if (n >= N_NODES) return;
    int bn = batch[n];
    int bp = (n == 0) ? -1 : batch[n - 1];
    for (int g = bp + 1; g <= bn; g++) g_goff[g] = n;
    if (n == N_NODES - 1) {
        for (int g = bn + 1; g <= G; g++) g_goff[g] = N_NODES;
    }
}

// ---------------- weight pre-convert to tf32 -------------------------------
__global__ void k_prepw(const float* __restrict__ Ws, const float* __restrict__ Wm) {
    int idx = blockIdx.x * blockDim.x + threadIdx.x;
    if (idx >= NUM_LAYERS * 2 * D * D) return;
    int l = idx / (2 * D * D);
    int r = (idx / D) % (2 * D);
    int n = idx % D;
    float v = (r < D) ? Ws[((size_t)l * D + r) * D + n]
                      : Wm[((size_t)l * D + (r - D)) * D + n];
    g_Wcat[idx] = f2tf(v);
}

// ---------------- fused gather + TF32 GEMM + epilogue ----------------------
// out = relu(X@Ws + S@Wm + bs + deg*bm), optional fused LayerNorm.
// BM=128 rows, BN=128 (=D), K=256 ([X|S]) in BK=32 chunks.
// 512 threads = 16 warps, warp grid 4(M) x 4(N), warp tile 32x32.

#define AS_STRIDE 260   // mod 32 = 4 -> a-frag bank 4*g + tig (unique)
#define BS_STRIDE 136   // mod 32 = 8 -> b-frag bank 8*tig + g (unique)
#define SMEM_BYTES ((128 * AS_STRIDE + 2 * 32 * BS_STRIDE) * 4 + 4 * 128 * 2 * 4)

__global__ void __launch_bounds__(512, 1)
k_conv(const float* __restrict__ X, const unsigned* __restrict__ Wcat,
       const float* __restrict__ bs, const float* __restrict__ bm,
       const float* __restrict__ lng, const float* __restrict__ lnb,
       int do_ln, float* __restrict__ out) {
    extern __shared__ unsigned char smem_raw[];
    unsigned* As = (unsigned*)smem_raw;                 // [128][AS_STRIDE]
    unsigned* Bs = As + 128 * AS_STRIDE;                // [2][32][BS_STRIDE]
    float* red_s = (float*)(Bs + 2 * 32 * BS_STRIDE);   // [4][128]
    float* red_q = red_s + 4 * 128;                     // [4][128]

    const int tid = threadIdx.x;
    const int m0 = blockIdx.x * 128;
    const int warpId = tid >> 5;
    const int warpM = warpId >> 2;        // 0..3
    const int warpN = warpId & 3;         // 0..3
    const int lane = tid & 31;
    const int g = lane >> 2;              // 0..7
    const int tig = lane & 3;             // 0..3

    // ---- phase 1: load X tile + gather S tile into As (tf32) --------------
    {
        const float4* X4 = (const float4*)X;
        for (int i = 0; i < 8; i++) {
            int r = warpId * 8 + i;
            int grow = m0 + r;
            uint4 ux = make_uint4(0u, 0u, 0u, 0u);
            uint4 us = make_uint4(0u, 0u, 0u, 0u);
            if (grow < N_NODES) {
                float4 xv = X4[(size_t)grow * 32 + lane];
                ux.x = f2tf(xv.x); ux.y = f2tf(xv.y);
                ux.z = f2tf(xv.z); ux.w = f2tf(xv.w);
                int s0 = g_rowptr[grow], s1 = g_rowptr[grow + 1];
                float4 a0 = make_float4(0.f, 0.f, 0.f, 0.f);
                float4 a1 = make_float4(0.f, 0.f, 0.f, 0.f);
                int e = s0;
                for (; e + 1 < s1; e += 2) {
                    int c0 = g_col[e], c1 = g_col[e + 1];
                    float4 v0 = X4[(size_t)c0 * 32 + lane];
                    float4 v1 = X4[(size_t)c1 * 32 + lane];
                    a0.x += v0.x; a0.y += v0.y; a0.z += v0.z; a0.w += v0.w;
                    a1.x += v1.x; a1.y += v1.y; a1.z += v1.z; a1.w += v1.w;
                }
                if (e < s1) {
                    float4 v0 = X4[(size_t)g_col[e] * 32 + lane];
                    a0.x += v0.x; a0.y += v0.y; a0.z += v0.z; a0.w += v0.w;
                }
                a0.x += a1.x; a0.y += a1.y; a0.z += a1.z; a0.w += a1.w;
                us.x = f2tf(a0.x); us.y = f2tf(a0.y);
                us.z = f2tf(a0.z); us.w = f2tf(a0.w);
            }
            *(uint4*)&As[r * AS_STRIDE + lane * 4] = ux;
            *(uint4*)&As[r * AS_STRIDE + 128 + lane * 4] = us;
        }
    }

    // ---- stage B chunk 0 --------------------------------------------------
#pragma unroll
    for (int i = 0; i < 2; i++) {
        int idx = tid + i * 512;           // 0..1023
        int k = idx >> 5, n4 = idx & 31;
        uint4 v = *(const uint4*)(Wcat + (size_t)k * D + n4 * 4);
        *(uint4*)&Bs[k * BS_STRIDE + n4 * 4] = v;
    }
    __syncthreads();

    // ---- phase 2: GEMM with double-buffered B -----------------------------
    float acc[2][4][4];
#pragma unroll
    for (int mt = 0; mt < 2; mt++)
#pragma unroll
        for (int nt = 0; nt < 4; nt++)
#pragma unroll
            for (int r = 0; r < 4; r++) acc[mt][nt][r] = 0.f;

    for (int kc = 0; kc < 8; kc++) {
        uint4 pre[2];
        if (kc < 7) {
#pragma unroll
            for (int i = 0; i < 2; i++) {
                int idx = tid + i * 512;
                int k = idx >> 5, n4 = idx & 31;
                pre[i] = *(const uint4*)(Wcat + (size_t)((kc + 1) * 32 + k) * D + n4 * 4);
            }
        }
        const unsigned* Bcur = Bs + (kc & 1) * 32 * BS_STRIDE;
#pragma unroll
        for (int ks = 0; ks < 4; ks++) {
            const int kof = kc * 32 + ks * 8;
            unsigned a[2][4], b[4][2];
#pragma unroll
            for (int mt = 0; mt < 2; mt++) {
                int r0 = warpM * 32 + mt * 16 + g;
                a[mt][0] = As[r0 * AS_STRIDE + kof + tig];
                a[mt][1] = As[(r0 + 8) * AS_STRIDE + kof + tig];
                a[mt][2] = As[r0 * AS_STRIDE + kof + tig + 4];
                a[mt][3] = As[(r0 + 8) * AS_STRIDE + kof + tig + 4];
            }
#pragma unroll
            for (int nt = 0; nt < 4; nt++) {
                int c = warpN * 32 + nt * 8 + g;
                b[nt][0] = Bcur[(ks * 8 + tig) * BS_STRIDE + c];
                b[nt][1] = Bcur[(ks * 8 + tig + 4) * BS_STRIDE + c];
            }
#pragma unroll
            for (int mt = 0; mt < 2; mt++)
#pragma unroll
                for (int nt = 0; nt < 4; nt++)
                    mma_tf32(acc[mt][nt], a[mt], b[nt]);
        }
        if (kc < 7) {
            unsigned* Bnxt = Bs + ((kc + 1) & 1) * 32 * BS_STRIDE;
#pragma unroll
            for (int i = 0; i < 2; i++) {
                int idx = tid + i * 512;
                int k = idx >> 5, n4 = idx & 31;
                *(uint4*)&Bnxt[k * BS_STRIDE + n4 * 4] = pre[i];
            }
        }
        __syncthreads();
    }

    // ---- epilogue: bias + deg*bm, relu, optional fused LayerNorm ----------
    float degf[2][2], s[2][2], q[2][2];
#pragma unroll
    for (int mt = 0; mt < 2; mt++)
#pragma unroll
        for (int h = 0; h < 2; h++) {
            int row = m0 + warpM * 32 + mt * 16 + h * 8 + g;
            degf[mt][h] = (row < N_NODES)
                ? (float)(g_rowptr[row + 1] - g_rowptr[row]) : 0.f;
            s[mt][h] = 0.f; q[mt][h] = 0.f;
        }

#pragma unroll
    for (int mt = 0; mt < 2; mt++)
#pragma unroll
        for (int nt = 0; nt < 4; nt++) {
            int c0 = warpN * 32 + nt * 8 + tig * 2;
            float bs0 = bs[c0], bs1 = bs[c0 + 1];
            float bm0 = bm[c0], bm1 = bm[c0 + 1];
#pragma unroll
            for (int h = 0; h < 2; h++) {
                float t0 = fmaxf(acc[mt][nt][h * 2 + 0] + bs0 + degf[mt][h] * bm0, 0.f);
                float t1 = fmaxf(acc[mt][nt][h * 2 + 1] + bs1 + degf[mt][h] * bm1, 0.f);
                acc[mt][nt][h * 2 + 0] = t0;
                acc[mt][nt][h * 2 + 1] = t1;
                s[mt][h] += t0 + t1;
                q[mt][h] += t0 * t0 + t1 * t1;
            }
        }

    if (do_ln) {
#pragma unroll
        for (int mt = 0; mt < 2; mt++)
#pragma unroll
            for (int h = 0; h < 2; h++) {
                float ss = s[mt][h], qq = q[mt][h];
                ss += __shfl_xor_sync(0xffffffffu, ss, 1);
                ss += __shfl_xor_sync(0xffffffffu, ss, 2);
                qq += __shfl_xor_sync(0xffffffffu, qq, 1);
                qq += __shfl_xor_sync(0xffffffffu, qq, 2);
                if (tig == 0) {
                    int rb = warpM * 32 + mt * 16 + h * 8 + g;
                    red_s[warpN * 128 + rb] = ss;
                    red_q[warpN * 128 + rb] = qq;
                }
            }
        __syncthreads();
#pragma unroll
        for (int mt = 0; mt < 2; mt++)
#pragma unroll
            for (int h = 0; h < 2; h++) {
                int rb = warpM * 32 + mt * 16 + h * 8 + g;
                int row = m0 + rb;
                if (row >= N_NODES) continue;
                float SS = red_s[rb] + red_s[128 + rb] + red_s[256 + rb] + red_s[384 + rb];
                float QQ = red_q[rb] + red_q[128 + rb] + red_q[256 + rb] + red_q[384 + rb];
                float mean = SS * (1.0f / D);
                float var = QQ * (1.0f / D) - mean * mean;
                float rstd = rsqrtf(var + EPS);
#pragma unroll
                for (int nt = 0; nt < 4; nt++) {
                    int c0 = warpN * 32 + nt * 8 + tig * 2;
                    float2 o;
                    o.x = lng[c0] * (acc[mt][nt][h * 2 + 0] - mean) * rstd + lnb[c0];
                    o.y = lng[c0 + 1] * (acc[mt][nt][h * 2 + 1] - mean) * rstd + lnb[c0 + 1];
                    *(float2*)(out + (size_t)row * D + c0) = o;
                }
            }
    } else {
#pragma unroll
        for (int mt = 0; mt < 2; mt++)
#pragma unroll
            for (int h = 0; h < 2; h++) {
                int row = m0 + warpM * 32 + mt * 16 + h * 8 + g;
                if (row >= N_NODES) continue;
#pragma unroll
                for (int nt = 0; nt < 4; nt++) {
                    int c0 = warpN * 32 + nt * 8 + tig * 2;
                    float2 o;
                    o.x = acc[mt][nt][h * 2 + 0];
                    o.y = acc[mt][nt][h * 2 + 1];
                    *(float2*)(out + (size_t)row * D + c0) = o;
                }
            }
    }
}

// ---------------- global mean pool (block per graph) -----------------------
__global__ void k_pool(const float* __restrict__ x) {
    int g = blockIdx.x, t = threadIdx.x;  // 128 threads
    int s = g_goff[g], e = g_goff[g + 1];
    float acc = 0.f;
    for (int n = s; n < e; n++) acc += x[(size_t)n * D + t];
    float cnt = (float)(e - s);
    if (cnt < 1.f) cnt = 1.f;
    g_pooled[g * D + t] = acc / cnt;
}

// ---------------- head: Linear(D,D) -> Linear(D,C) -> log_softmax ----------
__global__ void k_head(const float* __restrict__ W1, const float* __restrict__ b1,
                       const float* __restrict__ W2, const float* __restrict__ b2,
                       float* __restrict__ out) {
    __shared__ float p[D];
    __shared__ float h[D];
    int g = blockIdx.x, t = threadIdx.x;  // 128 threads
    p[t] = g_pooled[g * D + t];
    __syncthreads();
    float acc = b1[t];
#pragma unroll 8
    for (int k = 0; k < D; k++) acc += p[k] * W1[k * D + t];
    h[t] = acc;
    __syncthreads();
    if (t < C) {
        float a = b2[t];
#pragma unroll 8
        for (int k = 0; k < D; k++) a += h[k] * W2[k * C + t];
        float v = a;
        float mx = v;
#pragma unroll
        for (int off = 16; off > 0; off >>= 1)
            mx = fmaxf(mx, __shfl_xor_sync(0xffffffffu, mx, off));
        float ex = expf(v - mx);
        float sum = ex;
#pragma unroll
        for (int off = 16; off > 0; off >>= 1)
            sum += __shfl_xor_sync(0xffffffffu, sum, off);
        out[g * C + t] = v - mx - logf(sum);
    }
}

// ---------------- launch ---------------------------------------------------
extern "C" void kernel_launch(void* const* d_in, const int* in_sizes, int n_in,
                              void* d_out, int out_size) {
    const float* x      = (const float*)d_in[0];
    const float* W_self = (const float*)d_in[1];
    const float* b_self = (const float*)d_in[2];
    const float* W_msg  = (const float*)d_in[3];
    const float* b_msg  = (const float*)d_in[4];
    const float* ln_g   = (const float*)d_in[5];
    const float* ln_b   = (const float*)d_in[6];
    const float* W1     = (const float*)d_in[7];
    const float* b1     = (const float*)d_in[8];
    const float* W2     = (const float*)d_in[9];
    const float* b2     = (const float*)d_in[10];
    const int* ei       = (const int*)d_in[11];
    const int* batch    = (const int*)d_in[12];
    float* out          = (float*)d_out;

    float *bufA, *bufB;
    int* degp;
    unsigned* Wcat;
    cudaGetSymbolAddress((void**)&bufA, g_bufA);
    cudaGetSymbolAddress((void**)&bufB, g_bufB);
    cudaGetSymbolAddress((void**)&degp, g_deg);
    cudaGetSymbolAddress((void**)&Wcat, g_Wcat);

    static int smem_set = 0;
    if (!smem_set) {
        cudaFuncSetAttribute(k_conv, cudaFuncAttributeMaxDynamicSharedMemorySize,
                             SMEM_BYTES);
        smem_set = 1;
    }

    // CSR build + weight prep
    cudaMemsetAsync(degp, 0, N_NODES * sizeof(int));
    k_prepw<<<(NUM_LAYERS * 2 * D * D + 255) / 256, 256>>>(W_self, W_msg);
    k_count_deg<<<(N_EDGES + 255) / 256, 256>>>(ei);
    k_scan<<<1, 1024>>>();
    k_fill_csr<<<(N_EDGES + 255) / 256, 256>>>(ei);
    k_goff<<<(N_NODES + 255) / 256, 256>>>(batch);

    const int convBlocks = (N_NODES + 127) / 128;

    const float* xin = x;
    float* xout = bufA;
    for (int l = 0; l < NUM_LAYERS; l++) {
        int do_ln = (l < NUM_LAYERS - 1) ? 1 : 0;
        const float* lg = ln_g + (size_t)(do_ln ? l : 0) * D;
        const float* lb = ln_b + (size_t)(do_ln ? l : 0) * D;
        k_conv<<<convBlocks, 512, SMEM_BYTES>>>(
            xin, Wcat + (size_t)l * 2 * D * D,
            b_self + (size_t)l * D, b_msg + (size_t)l * D,
            lg, lb, do_ln, xout);
        xin = xout;
        xout = (xout == bufA) ? bufB : bufA;
    }

    k_pool<<<G, D>>>(xin);
    k_head<<<G, D>>>(W1, b1, W2, b2, out);
}

// round 9
// speedup vs baseline: 1.0234x; 1.0234x over previous
#include <cuda_runtime.h>
#include <cuda_bf16.h>
#include <math.h>

#define N_NODES 50000
#define N_EDGES 800000
#define D 128
#define C 32
#define G 64
#define EPS 1e-5f
#define NUM_LAYERS 3

// ---------------- scratch (device globals; no allocation allowed) ----------
__device__ float    g_bufA[N_NODES * D];
__device__ float    g_bufB[N_NODES * D];
__device__ float    g_S[N_NODES * D];
__device__ float    g_pooled[G * D];
__device__ unsigned g_Wcat[NUM_LAYERS * 2 * D * D];   // tf32 [l][256][128]
__device__ int      g_deg[N_NODES];
__device__ int      g_rowptr[N_NODES + 1];
__device__ int      g_cursor[N_NODES];
__device__ int      g_col[N_EDGES];
__device__ int      g_goff[G + 1];

__device__ __forceinline__ unsigned f2tf(float f) {
    unsigned u;
    asm("cvt.rna.tf32.f32 %0, %1;" : "=r"(u) : "f"(f));
    return u;
}

__device__ __forceinline__ void mma_tf32(float* d, const unsigned* a, const unsigned* b) {
    asm volatile(
        "mma.sync.aligned.m16n8k8.row.col.f32.tf32.tf32.f32 "
        "{%0,%1,%2,%3}, {%4,%5,%6,%7}, {%8,%9}, {%0,%1,%2,%3};"
        : "+f"(d[0]), "+f"(d[1]), "+f"(d[2]), "+f"(d[3])
        : "r"(a[0]), "r"(a[1]), "r"(a[2]), "r"(a[3]), "r"(b[0]), "r"(b[1]));
}

// ---------------- CSR build (4 edges per thread, int4 reads) ---------------
__global__ void k_count_deg(const int* __restrict__ ei) {
    int e = (blockIdx.x * blockDim.x + threadIdx.x) * 4;
    if (e + 3 < N_EDGES) {
        int4 d = *(const int4*)(ei + N_EDGES + e);
        atomicAdd(&g_deg[d.x], 1);
        atomicAdd(&g_deg[d.y], 1);
        atomicAdd(&g_deg[d.z], 1);
        atomicAdd(&g_deg[d.w], 1);
    } else {
        for (int i = e; i < N_EDGES; i++) atomicAdd(&g_deg[ei[N_EDGES + i]], 1);
    }
}

__global__ void k_scan() {
    __shared__ int s[1024];
    const int t = threadIdx.x;
    const int ITEMS = (N_NODES + 1023) / 1024;  // 49
    int base = t * ITEMS;
    int loc = 0;
    for (int i = 0; i < ITEMS; i++) {
        int idx = base + i;
        if (idx < N_NODES) loc += g_deg[idx];
    }
    s[t] = loc;
    __syncthreads();
    for (int off = 1; off < 1024; off <<= 1) {
        int v = 0;
        if (t >= off) v = s[t - off];
        __syncthreads();
        s[t] += v;
        __syncthreads();
    }
    int run = (t == 0) ? 0 : s[t - 1];
    for (int i = 0; i < ITEMS; i++) {
        int idx = base + i;
        if (idx < N_NODES) {
            g_rowptr[idx] = run;
            g_cursor[idx] = run;
            run += g_deg[idx];
        }
    }
    if (t == 1023) g_rowptr[N_NODES] = s[1023];
}

__global__ void k_fill_csr(const int* __restrict__ ei) {
    int e = (blockIdx.x * blockDim.x + threadIdx.x) * 4;
    if (e + 3 < N_EDGES) {
        int4 srcs = *(const int4*)(ei + e);
        int4 dsts = *(const int4*)(ei + N_EDGES + e);
        g_col[atomicAdd(&g_cursor[dsts.x], 1)] = srcs.x;
        g_col[atomicAdd(&g_cursor[dsts.y], 1)] = srcs.y;
        g_col[atomicAdd(&g_cursor[dsts.z], 1)] = srcs.z;
        g_col[atomicAdd(&g_cursor[dsts.w], 1)] = srcs.w;
    } else {
        for (int i = e; i < N_EDGES; i++) {
            int pos = atomicAdd(&g_cursor[ei[N_EDGES + i]], 1);
            g_col[pos] = ei[i];
        }
    }
}

__global__ void k_goff(const int* __restrict__ batch) {
    int n = blockIdx.x * blockDim.x + threadIdx.x;
    if (n >= N_NODES) return;
    int bn = batch[n];
    int bp = (n == 0) ? -1 : batch[n - 1];
    for (int g = bp + 1; g <= bn; g++) g_goff[g] = n;
    if (n == N_NODES - 1) {
        for (int g = bn + 1; g <= G; g++) g_goff[g] = N_NODES;
    }
}

// ---------------- weight pre-convert to tf32 -------------------------------
__global__ void k_prepw(const float* __restrict__ Ws, const float* __restrict__ Wm) {
    int idx = blockIdx.x * blockDim.x + threadIdx.x;
    if (idx >= NUM_LAYERS * 2 * D * D) return;
    int l = idx / (2 * D * D);
    int r = (idx / D) % (2 * D);
    int n = idx % D;
    float v = (r < D) ? Ws[((size_t)l * D + r) * D + n]
                      : Wm[((size_t)l * D + (r - D)) * D + n];
    g_Wcat[idx] = f2tf(v);
}

// ---------------- neighbor scatter-sum (warp per node, 4-wide MLP) ---------
__global__ void k_agg(const float* __restrict__ x, float* __restrict__ S) {
    int warp = (blockIdx.x * blockDim.x + threadIdx.x) >> 5;
    int lane = threadIdx.x & 31;
    if (warp >= N_NODES) return;
    const float4* X4 = (const float4*)x;
    int s0 = g_rowptr[warp], s1 = g_rowptr[warp + 1];
    float4 a0 = make_float4(0.f, 0.f, 0.f, 0.f);
    float4 a1 = make_float4(0.f, 0.f, 0.f, 0.f);
    float4 a2 = make_float4(0.f, 0.f, 0.f, 0.f);
    float4 a3 = make_float4(0.f, 0.f, 0.f, 0.f);
    int e = s0;
    for (; e + 3 < s1; e += 4) {
        int c0 = g_col[e], c1 = g_col[e + 1], c2 = g_col[e + 2], c3 = g_col[e + 3];
        float4 v0 = X4[(size_t)c0 * 32 + lane];
        float4 v1 = X4[(size_t)c1 * 32 + lane];
        float4 v2 = X4[(size_t)c2 * 32 + lane];
        float4 v3 = X4[(size_t)c3 * 32 + lane];
        a0.x += v0.x; a0.y += v0.y; a0.z += v0.z; a0.w += v0.w;
        a1.x += v1.x; a1.y += v1.y; a1.z += v1.z; a1.w += v1.w;
        a2.x += v2.x; a2.y += v2.y; a2.z += v2.z; a2.w += v2.w;
        a3.x += v3.x; a3.y += v3.y; a3.z += v3.z; a3.w += v3.w;
    }
    for (; e < s1; e++) {
        float4 v0 = X4[(size_t)g_col[e] * 32 + lane];
        a0.x += v0.x; a0.y += v0.y; a0.z += v0.z; a0.w += v0.w;
    }
    a0.x += a1.x + a2.x + a3.x;
    a0.y += a1.y + a2.y + a3.y;
    a0.z += a1.z + a2.z + a3.z;
    a0.w += a1.w + a2.w + a3.w;
    ((float4*)(S + (size_t)warp * D))[lane] = a0;
}

// ---------------- TF32 conv GEMM, double-buffered chunks -------------------
// out = relu(X@Ws + S@Wm + bs + deg*bm), optional fused LayerNorm.
// BM=128 rows, BN=128 (=D), K=256 ([X|S]) in BK=32 chunks, double-buffered.
// 512 threads = 16 warps, warp grid 4(M) x 4(N), warp tile 32x32.

#define AS_STRIDE 36    // mod 32 = 4 -> a-frag bank 4*g + tig (unique)
#define BS_STRIDE 136   // mod 32 = 8 -> b-frag bank 8*tig + g (unique)
#define SMEM_BYTES ((2 * 128 * AS_STRIDE + 2 * 32 * BS_STRIDE) * 4 + 4 * 128 * 2 * 4)

__global__ void __launch_bounds__(512, 2)
k_conv(const float* __restrict__ X, const float* __restrict__ S,
       const unsigned* __restrict__ Wcat,
       const float* __restrict__ bs, const float* __restrict__ bm,
       const float* __restrict__ lng, const float* __restrict__ lnb,
       int do_ln, float* __restrict__ out) {
    extern __shared__ unsigned char smem_raw[];
    unsigned* As = (unsigned*)smem_raw;                 // [2][128][AS_STRIDE]
    unsigned* Bs = As + 2 * 128 * AS_STRIDE;            // [2][32][BS_STRIDE]
    float* red_s = (float*)(Bs + 2 * 32 * BS_STRIDE);   // [4][128]
    float* red_q = red_s + 4 * 128;                     // [4][128]

    const int tid = threadIdx.x;
    const int m0 = blockIdx.x * 128;
    const int warpId = tid >> 5;
    const int warpM = warpId >> 2;        // 0..3
    const int warpN = warpId & 3;         // 0..3
    const int lane = tid & 31;
    const int g = lane >> 2;              // 0..7
    const int tig = lane & 3;             // 0..3

    // staging coords (2 slots each for A and B per thread)
    const int arow0 = tid >> 3, ak4 = tid & 7;          // A: idx = tid, tid+512
    const int arow1 = (tid + 512) >> 3;
    const int bk0 = tid >> 5, bn4 = tid & 31;           // B: idx = tid, tid+512
    const int bk1 = (tid + 512) >> 5;

    // ---- stage chunk 0 ----
    {
        const float* Asrc = X;  // kc=0
        float4 va0 = make_float4(0.f, 0.f, 0.f, 0.f), va1 = va0;
        if (m0 + arow0 < N_NODES)
            va0 = *(const float4*)(Asrc + (size_t)(m0 + arow0) * D + ak4 * 4);
        if (m0 + arow1 < N_NODES)
            va1 = *(const float4*)(Asrc + (size_t)(m0 + arow1) * D + ak4 * 4);
        uint4 u0, u1;
        u0.x = f2tf(va0.x); u0.y = f2tf(va0.y); u0.z = f2tf(va0.z); u0.w = f2tf(va0.w);
        u1.x = f2tf(va1.x); u1.y = f2tf(va1.y); u1.z = f2tf(va1.z); u1.w = f2tf(va1.w);
        *(uint4*)&As[arow0 * AS_STRIDE + ak4 * 4] = u0;
        *(uint4*)&As[arow1 * AS_STRIDE + ak4 * 4] = u1;
        *(uint4*)&Bs[bk0 * BS_STRIDE + bn4 * 4] = *(const uint4*)(Wcat + (size_t)bk0 * D + bn4 * 4);
        *(uint4*)&Bs[bk1 * BS_STRIDE + bn4 * 4] = *(const uint4*)(Wcat + (size_t)bk1 * D + bn4 * 4);
    }
    __syncthreads();

    float acc[2][4][4];
#pragma unroll
    for (int mt = 0; mt < 2; mt++)
#pragma unroll
        for (int nt = 0; nt < 4; nt++)
#pragma unroll
            for (int r = 0; r < 4; r++) acc[mt][nt][r] = 0.f;

    for (int kc = 0; kc < 8; kc++) {
        // prefetch next chunk into registers
        uint4 pa0, pa1, pb0, pb1;
        if (kc < 7) {
            int kn = kc + 1;
            const float* Asrc = (kn < 4) ? X : S;
            const int kbase = (kn & 3) * 32;
            float4 va0 = make_float4(0.f, 0.f, 0.f, 0.f), va1 = va0;
            if (m0 + arow0 < N_NODES)
                va0 = *(const float4*)(Asrc + (size_t)(m0 + arow0) * D + kbase + ak4 * 4);
            if (m0 + arow1 < N_NODES)
                va1 = *(const float4*)(Asrc + (size_t)(m0 + arow1) * D + kbase + ak4 * 4);
            pa0.x = f2tf(va0.x); pa0.y = f2tf(va0.y); pa0.z = f2tf(va0.z); pa0.w = f2tf(va0.w);
            pa1.x = f2tf(va1.x); pa1.y = f2tf(va1.y); pa1.z = f2tf(va1.z); pa1.w = f2tf(va1.w);
            pb0 = *(const uint4*)(Wcat + (size_t)(kn * 32 + bk0) * D + bn4 * 4);
            pb1 = *(const uint4*)(Wcat + (size_t)(kn * 32 + bk1) * D + bn4 * 4);
        }

        const unsigned* Acur = As + (kc & 1) * 128 * AS_STRIDE;
        const unsigned* Bcur = Bs + (kc & 1) * 32 * BS_STRIDE;
#pragma unroll
        for (int ks = 0; ks < 4; ks++) {
            const int kof = ks * 8;
            unsigned a[2][4], b[4][2];
#pragma unroll
            for (int mt = 0; mt < 2; mt++) {
                int r0 = warpM * 32 + mt * 16 + g;
                a[mt][0] = Acur[r0 * AS_STRIDE + kof + tig];
                a[mt][1] = Acur[(r0 + 8) * AS_STRIDE + kof + tig];
                a[mt][2] = Acur[r0 * AS_STRIDE + kof + tig + 4];
                a[mt][3] = Acur[(r0 + 8) * AS_STRIDE + kof + tig + 4];
            }
#pragma unroll
            for (int nt = 0; nt < 4; nt++) {
                int c = warpN * 32 + nt * 8 + g;
                b[nt][0] = Bcur[(kof + tig) * BS_STRIDE + c];
                b[nt][1] = Bcur[(kof + tig + 4) * BS_STRIDE + c];
            }
#pragma unroll
            for (int mt = 0; mt < 2; mt++)
#pragma unroll
                for (int nt = 0; nt < 4; nt++)
                    mma_tf32(acc[mt][nt], a[mt], b[nt]);
        }

        if (kc < 7) {
            unsigned* Anxt = As + ((kc + 1) & 1) * 128 * AS_STRIDE;
            unsigned* Bnxt = Bs + ((kc + 1) & 1) * 32 * BS_STRIDE;
            *(uint4*)&Anxt[arow0 * AS_STRIDE + ak4 * 4] = pa0;
            *(uint4*)&Anxt[arow1 * AS_STRIDE + ak4 * 4] = pa1;
            *(uint4*)&Bnxt[bk0 * BS_STRIDE + bn4 * 4] = pb0;
            *(uint4*)&Bnxt[bk1 * BS_STRIDE + bn4 * 4] = pb1;
            __syncthreads();
        }
    }

    // ---- epilogue: bias + deg*bm, relu, optional fused LayerNorm ----------
    float degf[2][2], s[2][2], q[2][2];
#pragma unroll
    for (int mt = 0; mt < 2; mt++)
#pragma unroll
        for (int h = 0; h < 2; h++) {
            int row = m0 + warpM * 32 + mt * 16 + h * 8 + g;
            degf[mt][h] = (row < N_NODES)
                ? (float)(g_rowptr[row + 1] - g_rowptr[row]) : 0.f;
            s[mt][h] = 0.f; q[mt][h] = 0.f;
        }

#pragma unroll
    for (int mt = 0; mt < 2; mt++)
#pragma unroll
        for (int nt = 0; nt < 4; nt++) {
            int c0 = warpN * 32 + nt * 8 + tig * 2;
            float bs0 = bs[c0], bs1 = bs[c0 + 1];
            float bm0 = bm[c0], bm1 = bm[c0 + 1];
#pragma unroll
            for (int h = 0; h < 2; h++) {
                float t0 = fmaxf(acc[mt][nt][h * 2 + 0] + bs0 + degf[mt][h] * bm0, 0.f);
                float t1 = fmaxf(acc[mt][nt][h * 2 + 1] + bs1 + degf[mt][h] * bm1, 0.f);
                acc[mt][nt][h * 2 + 0] = t0;
                acc[mt][nt][h * 2 + 1] = t1;
                s[mt][h] += t0 + t1;
                q[mt][h] += t0 * t0 + t1 * t1;
            }
        }

    if (do_ln) {
#pragma unroll
        for (int mt = 0; mt < 2; mt++)
#pragma unroll
            for (int h = 0; h < 2; h++) {
                float ss = s[mt][h], qq = q[mt][h];
                ss += __shfl_xor_sync(0xffffffffu, ss, 1);
                ss += __shfl_xor_sync(0xffffffffu, ss, 2);
                qq += __shfl_xor_sync(0xffffffffu, qq, 1);
                qq += __shfl_xor_sync(0xffffffffu, qq, 2);
                if (tig == 0) {
                    int rb = warpM * 32 + mt * 16 + h * 8 + g;
                    red_s[warpN * 128 + rb] = ss;
                    red_q[warpN * 128 + rb] = qq;
                }
            }
        __syncthreads();
#pragma unroll
        for (int mt = 0; mt < 2; mt++)
#pragma unroll
            for (int h = 0; h < 2; h++) {
                int rb = warpM * 32 + mt * 16 + h * 8 + g;
                int row = m0 + rb;
                if (row >= N_NODES) continue;
                float SS = red_s[rb] + red_s[128 + rb] + red_s[256 + rb] + red_s[384 + rb];
                float QQ = red_q[rb] + red_q[128 + rb] + red_q[256 + rb] + red_q[384 + rb];
                float mean = SS * (1.0f / D);
                float var = QQ * (1.0f / D) - mean * mean;
                float rstd = rsqrtf(var + EPS);
#pragma unroll
                for (int nt = 0; nt < 4; nt++) {
                    int c0 = warpN * 32 + nt * 8 + tig * 2;
                    float2 o;
                    o.x = lng[c0] * (acc[mt][nt][h * 2 + 0] - mean) * rstd + lnb[c0];
                    o.y = lng[c0 + 1] * (acc[mt][nt][h * 2 + 1] - mean) * rstd + lnb[c0 + 1];
                    *(float2*)(out + (size_t)row * D + c0) = o;
                }
            }
    } else {
#pragma unroll
        for (int mt = 0; mt < 2; mt++)
#pragma unroll
            for (int h = 0; h < 2; h++) {
                int row = m0 + warpM * 32 + mt * 16 + h * 8 + g;
                if (row >= N_NODES) continue;
#pragma unroll
                for (int nt = 0; nt < 4; nt++) {
                    int c0 = warpN * 32 + nt * 8 + tig * 2;
                    float2 o;
                    o.x = acc[mt][nt][h * 2 + 0];
                    o.y = acc[mt][nt][h * 2 + 1];
                    *(float2*)(out + (size_t)row * D + c0) = o;
                }
            }
    }
}

// ---------------- global mean pool (block per graph) -----------------------
__global__ void k_pool(const float* __restrict__ x) {
    int g = blockIdx.x, t = threadIdx.x;  // 128 threads
    int s = g_goff[g], e = g_goff[g + 1];
    float acc = 0.f;
    for (int n = s; n < e; n++) acc += x[(size_t)n * D + t];
    float cnt = (float)(e - s);
    if (cnt < 1.f) cnt = 1.f;
    g_pooled[g * D + t] = acc / cnt;
}

// ---------------- head: Linear(D,D) -> Linear(D,C) -> log_softmax ----------
__global__ void k_head(const float* __restrict__ W1, const float* __restrict__ b1,
                       const float* __restrict__ W2, const float* __restrict__ b2,
                       float* __restrict__ out) {
    __shared__ float p[D];
    __shared__ float h[D];
    int g = blockIdx.x, t = threadIdx.x;  // 128 threads
    p[t] = g_pooled[g * D + t];
    __syncthreads();
    float acc = b1[t];
#pragma unroll 8
    for (int k = 0; k < D; k++) acc += p[k] * W1[k * D + t];
    h[t] = acc;
    __syncthreads();
    if (t < C) {
        float a = b2[t];
#pragma unroll 8
        for (int k = 0; k < D; k++) a += h[k] * W2[k * C + t];
        float v = a;
        float mx = v;
#pragma unroll
        for (int off = 16; off > 0; off >>= 1)
            mx = fmaxf(mx, __shfl_xor_sync(0xffffffffu, mx, off));
        float ex = expf(v - mx);
        float sum = ex;
#pragma unroll
        for (int off = 16; off > 0; off >>= 1)
            sum += __shfl_xor_sync(0xffffffffu, sum, off);
        out[g * C + t] = v - mx - logf(sum);
    }
}

// ---------------- launch ---------------------------------------------------
extern "C" void kernel_launch(void* const* d_in, const int* in_sizes, int n_in,
                              void* d_out, int out_size) {
    const float* x      = (const float*)d_in[0];
    const float* W_self = (const float*)d_in[1];
    const float* b_self = (const float*)d_in[2];
    const float* W_msg  = (const float*)d_in[3];
    const float* b_msg  = (const float*)d_in[4];
    const float* ln_g   = (const float*)d_in[5];
    const float* ln_b   = (const float*)d_in[6];
    const float* W1     = (const float*)d_in[7];
    const float* b1     = (const float*)d_in[8];
    const float* W2     = (const float*)d_in[9];
    const float* b2     = (const float*)d_in[10];
    const int* ei       = (const int*)d_in[11];
    const int* batch    = (const int*)d_in[12];
    float* out          = (float*)d_out;

    float *bufA, *bufB, *S;
    int* degp;
    unsigned* Wcat;
    cudaGetSymbolAddress((void**)&bufA, g_bufA);
    cudaGetSymbolAddress((void**)&bufB, g_bufB);
    cudaGetSymbolAddress((void**)&S, g_S);
    cudaGetSymbolAddress((void**)&degp, g_deg);
    cudaGetSymbolAddress((void**)&Wcat, g_Wcat);

    static int smem_set = 0;
    if (!smem_set) {
        cudaFuncSetAttribute(k_conv, cudaFuncAttributeMaxDynamicSharedMemorySize,
                             SMEM_BYTES);
        smem_set = 1;
    }

    // CSR build + weight prep
    cudaMemsetAsync(degp, 0, N_NODES * sizeof(int));
    k_prepw<<<(NUM_LAYERS * 2 * D * D + 255) / 256, 256>>>(W_self, W_msg);
    k_count_deg<<<(N_EDGES / 4 + 255) / 256, 256>>>(ei);
    k_scan<<<1, 1024>>>();
    k_fill_csr<<<(N_EDGES / 4 + 255) / 256, 256>>>(ei);
    k_goff<<<(N_NODES + 255) / 256, 256>>>(batch);

    const int aggBlocks = (N_NODES * 32 + 255) / 256;
    const int convBlocks = (N_NODES + 127) / 128;

    const float* xin = x;
    float* xout = bufA;
    for (int l = 0; l < NUM_LAYERS; l++) {
        int do_ln = (l < NUM_LAYERS - 1) ? 1 : 0;
        const float* lg = ln_g + (size_t)(do_ln ? l : 0) * D;
        const float* lb = ln_b + (size_t)(do_ln ? l : 0) * D;
        k_agg<<<aggBlocks, 256>>>(xin, S);
        k_conv<<<convBlocks, 512, SMEM_BYTES>>>(
            xin, S, Wcat + (size_t)l * 2 * D * D,
            b_self + (size_t)l * D, b_msg + (size_t)l * D,
            lg, lb, do_ln, xout);
        xin = xout;
        xout = (xout == bufA) ? bufB : bufA;
    }

    k_pool<<<G, D>>>(xin);
    k_head<<<G, D>>>(W1, b1, W2, b2, out);
}